// round 7
// baseline (speedup 1.0000x reference)
#include <cuda_runtime.h>
#include <cuda_bf16.h>
#include <cuda_fp16.h>

#define NCI 16
#define NCO 32
#define NBR 3
#define NTERM (NCI * 9 * NBR)   // 432 per co
#define HH 32
#define WW 32
#define NBATCH 4

__device__ __forceinline__ __half2 tanh2_approx(__half2 x) {
    unsigned xi = *(unsigned*)&x;
    unsigned yi;
    asm("tanh.approx.f16x2 %0, %1;" : "=r"(yi) : "r"(xi));
    return *(__half2*)&yi;
}

// Block = (b, co, 4-row tile). 192 threads = 3 nb-groups x 64 threads.
// Each thread: 2 vertically adjacent pixels, ONE nb branch, all 16 ci.
// x tile stored in smem as vertical-pair half2; all basis math f16x2.
__global__ __launch_bounds__(192, 8)
void ferro_main_kernel(const float* __restrict__ x,
                       const float* __restrict__ k,
                       const float* __restrict__ Ec,
                       const float* __restrict__ Ps,
                       const float* __restrict__ bias,
                       const float* __restrict__ coef,
                       const float* __restrict__ out_bias,
                       float* __restrict__ out) {
    __shared__ uint4   sA[NTERM];         // {h2(5Ec), h2(k), h2(0.9kEc), h2(0.1kEc)}
    __shared__ float   sC[NTERM];         // coef*Ps (f32)
    __shared__ __half2 sxp[NCI][5][34];   // vertical-pair rows, zero padded cols
    __shared__ float   sP[128][2];        // partials from nb-groups 1 and 2
    __shared__ float   sRed[6];

    int tid  = threadIdx.x;
    int tile = blockIdx.x & 7;            // 8 tiles of 4 output rows
    int co   = (blockIdx.x >> 3) & 31;
    int b    = blockIdx.x >> 8;
    int r0   = tile * 4;

    // ---- stage x tile as vertical-pair half2: 16 ci x 5 rr x 8 col-groups = 640
    #pragma unroll
    for (int i = 0; i < 4; i++) {
        int idx = tid + i * 192;
        if (idx < 640) {
            int c4  = idx & 7;
            int rr  = (idx >> 3) % 5;
            int ci  = idx / 40;
            int g0  = r0 - 1 + rr;        // pixel-0 tap row
            int g1  = r0 + rr;            // pixel-1 tap row
            const float* base = x + ((b * NCI + ci) * HH) * WW + c4 * 4;
            float4 v0 = make_float4(0.f, 0.f, 0.f, 0.f);
            float4 v1 = make_float4(0.f, 0.f, 0.f, 0.f);
            if ((unsigned)g0 < 32u) v0 = *(const float4*)(base + g0 * WW);
            if ((unsigned)g1 < 32u) v1 = *(const float4*)(base + g1 * WW);
            int cb0 = c4 * 4 + 1;
            sxp[ci][rr][cb0 + 0] = __floats2half2_rn(v0.x, v1.x);
            sxp[ci][rr][cb0 + 1] = __floats2half2_rn(v0.y, v1.y);
            sxp[ci][rr][cb0 + 2] = __floats2half2_rn(v0.z, v1.z);
            sxp[ci][rr][cb0 + 3] = __floats2half2_rn(v0.w, v1.w);
        }
    }
    if (tid < 80) {                       // zero pad columns: 16 ci x 5 rr
        int ci = tid / 5, rr = tid % 5;
        sxp[ci][rr][0]  = __float2half2_rn(0.f);
        sxp[ci][rr][33] = __float2half2_rn(0.f);
    }

    // ---- pack params for this co (432 terms = 108 float4 groups)
    float cb = 0.0f;
    if (tid < NTERM / 4) {
        const float4* k4 = (const float4*)(k    + co * NTERM);
        const float4* e4 = (const float4*)(Ec   + co * NTERM);
        const float4* p4 = (const float4*)(Ps   + co * NTERM);
        const float4* b4 = (const float4*)(bias + co * NTERM);
        const float4* c4 = (const float4*)(coef + co * NTERM);
        float4 kk = k4[tid], ee = e4[tid], pp = p4[tid], bb = b4[tid], cc = c4[tid];
        float kkv[4] = {kk.x, kk.y, kk.z, kk.w};
        float eev[4] = {ee.x, ee.y, ee.z, ee.w};
        float ppv[4] = {pp.x, pp.y, pp.z, pp.w};
        float bbv[4] = {bb.x, bb.y, bb.z, bb.w};
        float ccv[4] = {cc.x, cc.y, cc.z, cc.w};
        #pragma unroll
        for (int j = 0; j < 4; j++) {
            float ke = kkv[j] * eev[j];
            __half2 e5 = __float2half2_rn(5.0f * eev[j]);
            __half2 kh = __float2half2_rn(kkv[j]);
            __half2 z9 = __float2half2_rn(0.9f * ke);
            __half2 w1 = __float2half2_rn(0.1f * ke);
            uint4 u;
            u.x = *(unsigned*)&e5;
            u.y = *(unsigned*)&kh;
            u.z = *(unsigned*)&z9;
            u.w = *(unsigned*)&w1;
            sA[tid * 4 + j] = u;
            sC[tid * 4 + j] = ccv[j] * ppv[j];
            cb += ccv[j] * bbv[j];
        }
    }
    // block-reduce cb (position-independent term)
    #pragma unroll
    for (int s = 16; s > 0; s >>= 1)
        cb += __shfl_xor_sync(0xFFFFFFFFu, cb, s);
    if ((tid & 31) == 0) sRed[tid >> 5] = cb;
    __syncthreads();
    float bc = ((sRed[0] + sRed[1]) + (sRed[2] + sRed[3])) + (sRed[4] + sRed[5])
             + out_bias[co];

    int nb = tid / 64;        // nb-group: 0..2
    int t  = tid & 63;
    int wo = t & 31;          // output col
    int lr = t >> 5;          // 0..1 -> rows r0+2lr, r0+2lr+1

    float acc0 = 0.f, acc1 = 0.f;

    #pragma unroll 1
    for (int ci = 0; ci < NCI; ci++) {
        // 9 taps, both pixels packed: xh = {x[p0 tap], x[p1 tap]}
        __half2 xh[9];
        #pragma unroll
        for (int dy = 0; dy < 3; dy++)
            #pragma unroll
            for (int dx = 0; dx < 3; dx++)
                xh[dy * 3 + dx] = sxp[ci][2 * lr + dy][wo + dx];

        const uint4* pa = &sA[(ci * NBR + nb) * 9];
        const float* pc = &sC[(ci * NBR + nb) * 9];
        const __half2 FIVE2 = __float2half2_rn(5.0f);
        #pragma unroll
        for (int ij = 0; ij < 9; ij++) {
            uint4 u  = pa[ij];
            float cp = pc[ij];
            __half2 e5 = *(__half2*)&u.x;
            __half2 kh = *(__half2*)&u.y;
            __half2 z9 = *(__half2*)&u.z;
            __half2 w1 = *(__half2*)&u.w;
            __half2 xp = xh[ij];
            __half2 g  = __hfma2(xp, kh, z9);             // overlaps MUFU-1
            __half2 t1 = tanh2_approx(__hfma2(xp, FIVE2, e5));
            __half2 t2 = tanh2_approx(__hfma2(t1, w1, g));
            acc0 = fmaf(cp, __low2float(t2),  acc0);
            acc1 = fmaf(cp, __high2float(t2), acc1);
        }
    }

    if (nb > 0) {
        sP[(nb - 1) * 64 + t][0] = acc0;
        sP[(nb - 1) * 64 + t][1] = acc1;
    }
    __syncthreads();
    if (nb == 0) {
        int ho = r0 + 2 * lr;
        float* op = out + (((b * NCO + co) * HH + ho) * WW) + wo;
        op[0]  = ((acc0 + sP[t][0]) + (sP[64 + t][0] + bc));
        op[WW] = ((acc1 + sP[t][1]) + (sP[64 + t][1] + bc));
    }
}

extern "C" void kernel_launch(void* const* d_in, const int* in_sizes, int n_in,
                              void* d_out, int out_size) {
    const float* x        = (const float*)d_in[0];
    const float* k        = (const float*)d_in[1];
    const float* Ec       = (const float*)d_in[2];
    const float* Ps       = (const float*)d_in[3];
    const float* bias     = (const float*)d_in[4];
    const float* coef     = (const float*)d_in[5];
    const float* out_bias = (const float*)d_in[6];
    float* out = (float*)d_out;

    ferro_main_kernel<<<NBATCH * NCO * 8, 192>>>(x, k, Ec, Ps, bias, coef, out_bias, out);
}

// round 8
// speedup vs baseline: 1.0487x; 1.0487x over previous
#include <cuda_runtime.h>
#include <cuda_bf16.h>
#include <cuda_fp16.h>

#define NCI 16
#define NCO 32
#define NBR 3
#define NTERM (NCI * 9 * NBR)   // 432 per co
#define HH 32
#define WW 32
#define NBATCH 4

__device__ __forceinline__ __half2 tanh2_approx(__half2 x) {
    unsigned xi = *(unsigned*)&x;
    unsigned yi;
    asm("tanh.approx.f16x2 %0, %1;" : "=r"(yi) : "r"(xi));
    return *(__half2*)&yi;
}

// Block = (b, co, 4-row tile). 128 threads = 2 ci-groups x 64 threads.
// Each thread: 2 vertically adjacent pixels, 8 of 16 input channels.
// Inner tanh for nb in {0,1}: 32-segment PWL via register table + shfl (no MUFU).
// Inner tanh for nb==2 and all outer tanh: MUFU f16x2.
__global__ __launch_bounds__(128, 7)
void ferro_main_kernel(const float* __restrict__ x,
                       const float* __restrict__ k,
                       const float* __restrict__ Ec,
                       const float* __restrict__ Ps,
                       const float* __restrict__ bias,
                       const float* __restrict__ coef,
                       const float* __restrict__ out_bias,
                       float* __restrict__ out) {
    __shared__ uint4   sA[NTERM];         // {h2(5Ec), h2(k), h2(0.9kEc), h2(0.1kEc)}
    __shared__ float   sC[NTERM];         // coef*Ps (f32)
    __shared__ __half2 sxp[NCI][5][34];   // vertical-pair rows, zero padded cols
    __shared__ float   sP[64][2];         // group-1 partials
    __shared__ float   sRed[4];

    int tid  = threadIdx.x;
    int lane = tid & 31;
    int tile = blockIdx.x & 7;            // 8 tiles of 4 output rows
    int co   = (blockIdx.x >> 3) & 31;
    int b    = blockIdx.x >> 8;
    int r0   = tile * 4;

    // ---- per-lane PWL table for tanh on [-4,4]: lane L owns segment L.
    // minimax-adjusted chord: continuous-ish, |err| ~ 3e-3.
    unsigned tbl;
    {
        float ya = -4.0f + 0.25f * lane;
        float yb = ya + 0.25f;
        float ta = tanhf(ya), tb = tanhf(yb);
        float s  = (tb - ta) * 4.0f;
        float bi = ta - s * ya + 0.5f * (tanhf(ya + 0.125f) - 0.5f * (ta + tb));
        __half2 sb = __floats2half2_rn(s, bi);    // low = slope, high = intercept
        tbl = *(unsigned*)&sb;
    }

    // ---- stage x tile as vertical-pair half2: 16 ci x 5 rr x 8 col-groups = 640
    #pragma unroll
    for (int i = 0; i < 5; i++) {
        int idx = tid + i * 128;
        int c4  = idx & 7;
        int rr  = (idx >> 3) % 5;
        int ci  = idx / 40;
        int g0  = r0 - 1 + rr;            // pixel-0 tap row
        int g1  = r0 + rr;                // pixel-1 tap row
        const float* base = x + ((b * NCI + ci) * HH) * WW + c4 * 4;
        float4 v0 = make_float4(0.f, 0.f, 0.f, 0.f);
        float4 v1 = make_float4(0.f, 0.f, 0.f, 0.f);
        if ((unsigned)g0 < 32u) v0 = *(const float4*)(base + g0 * WW);
        if ((unsigned)g1 < 32u) v1 = *(const float4*)(base + g1 * WW);
        int cb0 = c4 * 4 + 1;
        sxp[ci][rr][cb0 + 0] = __floats2half2_rn(v0.x, v1.x);
        sxp[ci][rr][cb0 + 1] = __floats2half2_rn(v0.y, v1.y);
        sxp[ci][rr][cb0 + 2] = __floats2half2_rn(v0.z, v1.z);
        sxp[ci][rr][cb0 + 3] = __floats2half2_rn(v0.w, v1.w);
    }
    if (tid < 80) {                       // zero pad columns: 16 ci x 5 rr
        int ci = tid / 5, rr = tid % 5;
        sxp[ci][rr][0]  = __float2half2_rn(0.f);
        sxp[ci][rr][33] = __float2half2_rn(0.f);
    }

    // ---- pack params for this co (432 terms = 108 float4 groups)
    float cb = 0.0f;
    if (tid < NTERM / 4) {
        const float4* k4 = (const float4*)(k    + co * NTERM);
        const float4* e4 = (const float4*)(Ec   + co * NTERM);
        const float4* p4 = (const float4*)(Ps   + co * NTERM);
        const float4* b4 = (const float4*)(bias + co * NTERM);
        const float4* c4 = (const float4*)(coef + co * NTERM);
        float4 kk = k4[tid], ee = e4[tid], pp = p4[tid], bb = b4[tid], cc = c4[tid];
        float kkv[4] = {kk.x, kk.y, kk.z, kk.w};
        float eev[4] = {ee.x, ee.y, ee.z, ee.w};
        float ppv[4] = {pp.x, pp.y, pp.z, pp.w};
        float bbv[4] = {bb.x, bb.y, bb.z, bb.w};
        float ccv[4] = {cc.x, cc.y, cc.z, cc.w};
        #pragma unroll
        for (int j = 0; j < 4; j++) {
            float ke = kkv[j] * eev[j];
            __half2 e5 = __float2half2_rn(5.0f * eev[j]);
            __half2 kh = __float2half2_rn(kkv[j]);
            __half2 z9 = __float2half2_rn(0.9f * ke);
            __half2 w1 = __float2half2_rn(0.1f * ke);
            uint4 u;
            u.x = *(unsigned*)&e5;
            u.y = *(unsigned*)&kh;
            u.z = *(unsigned*)&z9;
            u.w = *(unsigned*)&w1;
            sA[tid * 4 + j] = u;
            sC[tid * 4 + j] = ccv[j] * ppv[j];
            cb += ccv[j] * bbv[j];
        }
    }
    // block-reduce cb (position-independent term)
    #pragma unroll
    for (int s = 16; s > 0; s >>= 1)
        cb += __shfl_xor_sync(0xFFFFFFFFu, cb, s);
    if ((tid & 31) == 0) sRed[tid >> 5] = cb;
    __syncthreads();
    float bc = (sRed[0] + sRed[1]) + (sRed[2] + sRed[3]) + out_bias[co];

    int cig = tid >> 6;       // ci-group: 0 or 1 (8 channels each)
    int t   = tid & 63;
    int wo  = t & 31;         // output col
    int lr  = t >> 5;         // 0..1 -> rows r0+2lr, r0+2lr+1

    const __half2 FIVE2 = __float2half2_rn(5.0f);
    const __half2 FOUR2 = __float2half2_rn(4.0f);
    const __half2 OFF2  = __float2half2_rn(16.0f);
    const __half2 M4    = __float2half2_rn(-4.0f);
    const __half2 P4    = __float2half2_rn(3.99609375f);  // largest f16 < 4

    float acc[6] = {0.f, 0.f, 0.f, 0.f, 0.f, 0.f};

    #pragma unroll 1
    for (int ci8 = 0; ci8 < 8; ci8++) {
        int ci = cig * 8 + ci8;
        __half2 xh[9];
        #pragma unroll
        for (int dy = 0; dy < 3; dy++)
            #pragma unroll
            for (int dx = 0; dx < 3; dx++)
                xh[dy * 3 + dx] = sxp[ci][2 * lr + dy][wo + dx];

        const uint4* pa = &sA[ci * 27];
        const float* pc = &sC[ci * 27];
        #pragma unroll
        for (int nb = 0; nb < NBR; nb++) {
            #pragma unroll
            for (int ij = 0; ij < 9; ij++) {
                uint4 u  = pa[nb * 9 + ij];
                float cp = pc[nb * 9 + ij];
                __half2 e5 = *(__half2*)&u.x;
                __half2 kh = *(__half2*)&u.y;
                __half2 z9 = *(__half2*)&u.z;
                __half2 w1 = *(__half2*)&u.w;
                __half2 xp = xh[ij];
                __half2 y  = __hfma2(xp, FIVE2, e5);   // 5x + 5Ec
                __half2 g  = __hfma2(xp, kh, z9);      // kx + 0.9kEc
                __half2 t1;
                if (nb < 2) {
                    // PWL inner tanh: clamp y, index = 4*yc + 16, shfl table
                    __half2 yc = __hmax2(y, M4);
                    yc = __hmin2(yc, P4);
                    __half2 f = __hfma2(yc, FOUR2, OFF2);
                    int i0 = __half2int_rd(__low2half(f));
                    int i1 = __half2int_rd(__high2half(f));
                    unsigned p0 = __shfl_sync(0xFFFFFFFFu, tbl, i0);
                    unsigned p1 = __shfl_sync(0xFFFFFFFFu, tbl, i1);
                    unsigned s2 = __byte_perm(p0, p1, 0x5410);  // {s0, s1}
                    unsigned b2 = __byte_perm(p0, p1, 0x7632);  // {b0, b1}
                    t1 = __hfma2(*(__half2*)&s2, yc, *(__half2*)&b2);
                } else {
                    t1 = tanh2_approx(y);
                }
                __half2 t2 = tanh2_approx(__hfma2(t1, w1, g));
                acc[nb * 2 + 0] = fmaf(cp, __low2float(t2),  acc[nb * 2 + 0]);
                acc[nb * 2 + 1] = fmaf(cp, __high2float(t2), acc[nb * 2 + 1]);
            }
        }
    }

    float r0v = (acc[0] + acc[2]) + acc[4];
    float r1v = (acc[1] + acc[3]) + acc[5];

    if (cig == 1) {
        sP[t][0] = r0v;
        sP[t][1] = r1v;
    }
    __syncthreads();
    if (cig == 0) {
        int ho = r0 + 2 * lr;
        float* op = out + (((b * NCO + co) * HH + ho) * WW) + wo;
        op[0]  = (r0v + sP[t][0]) + bc;
        op[WW] = (r1v + sP[t][1]) + bc;
    }
}

extern "C" void kernel_launch(void* const* d_in, const int* in_sizes, int n_in,
                              void* d_out, int out_size) {
    const float* x        = (const float*)d_in[0];
    const float* k        = (const float*)d_in[1];
    const float* Ec       = (const float*)d_in[2];
    const float* Ps       = (const float*)d_in[3];
    const float* bias     = (const float*)d_in[4];
    const float* coef     = (const float*)d_in[5];
    const float* out_bias = (const float*)d_in[6];
    float* out = (float*)d_out;

    ferro_main_kernel<<<NBATCH * NCO * 8, 128>>>(x, k, Ec, Ps, bias, coef, out_bias, out);
}

// round 9
// speedup vs baseline: 1.0928x; 1.0421x over previous
#include <cuda_runtime.h>
#include <cuda_bf16.h>
#include <cuda_fp16.h>

#define NCI 16
#define NCO 32
#define NBR 3
#define NTERM (NCI * 9 * NBR)   // 432 per co
#define HH 32
#define WW 32
#define NBATCH 4

__device__ __forceinline__ __half2 tanh2_approx(__half2 x) {
    unsigned xi = *(unsigned*)&x;
    unsigned yi;
    asm("tanh.approx.f16x2 %0, %1;" : "=r"(yi) : "r"(xi));
    return *(__half2*)&yi;
}

// Block = (b, co, 4-row tile). 128 threads = 4 ci-groups x 32 cols.
// Each thread: ALL 4 pixels of its tile column (2 vertical half2 pairs),
// 4 of 16 input channels. One param LDS feeds both pairs.
__global__ __launch_bounds__(128, 7)
void ferro_main_kernel(const float* __restrict__ x,
                       const float* __restrict__ k,
                       const float* __restrict__ Ec,
                       const float* __restrict__ Ps,
                       const float* __restrict__ bias,
                       const float* __restrict__ coef,
                       const float* __restrict__ out_bias,
                       float* __restrict__ out) {
    __shared__ uint4   sA[NTERM];         // {h2(5Ec), h2(k), h2(0.9kEc), h2(0.1kEc)}
    __shared__ float   sC[NTERM];         // coef*Ps (f32)
    __shared__ __half2 sxp[NCI][5][34];   // sliding vertical-pair rows, padded cols
    __shared__ float   sP[3][32][4];      // partials from ci-groups 1..3
    __shared__ float   sRed[4];

    int tid  = threadIdx.x;
    int tile = blockIdx.x & 7;            // 8 tiles of 4 output rows
    int co   = (blockIdx.x >> 3) & 31;
    int b    = blockIdx.x >> 8;
    int r0   = tile * 4;

    // ---- stage x tile as vertical-pair half2: 16 ci x 5 rr x 8 col-groups = 640
    #pragma unroll
    for (int i = 0; i < 5; i++) {
        int idx = tid + i * 128;
        int c4  = idx & 7;
        int rr  = (idx >> 3) % 5;
        int ci  = idx / 40;
        int g0  = r0 - 1 + rr;            // low-half tap row
        int g1  = r0 + rr;                // high-half tap row
        const float* base = x + ((b * NCI + ci) * HH) * WW + c4 * 4;
        float4 v0 = make_float4(0.f, 0.f, 0.f, 0.f);
        float4 v1 = make_float4(0.f, 0.f, 0.f, 0.f);
        if ((unsigned)g0 < 32u) v0 = *(const float4*)(base + g0 * WW);
        if ((unsigned)g1 < 32u) v1 = *(const float4*)(base + g1 * WW);
        int cb0 = c4 * 4 + 1;
        sxp[ci][rr][cb0 + 0] = __floats2half2_rn(v0.x, v1.x);
        sxp[ci][rr][cb0 + 1] = __floats2half2_rn(v0.y, v1.y);
        sxp[ci][rr][cb0 + 2] = __floats2half2_rn(v0.z, v1.z);
        sxp[ci][rr][cb0 + 3] = __floats2half2_rn(v0.w, v1.w);
    }
    if (tid < 80) {                       // zero pad columns: 16 ci x 5 rr
        int ci = tid / 5, rr = tid % 5;
        sxp[ci][rr][0]  = __float2half2_rn(0.f);
        sxp[ci][rr][33] = __float2half2_rn(0.f);
    }

    // ---- pack params for this co (432 terms = 108 float4 groups)
    float cb = 0.0f;
    if (tid < NTERM / 4) {
        const float4* k4 = (const float4*)(k    + co * NTERM);
        const float4* e4 = (const float4*)(Ec   + co * NTERM);
        const float4* p4 = (const float4*)(Ps   + co * NTERM);
        const float4* b4 = (const float4*)(bias + co * NTERM);
        const float4* c4 = (const float4*)(coef + co * NTERM);
        float4 kk = k4[tid], ee = e4[tid], pp = p4[tid], bb = b4[tid], cc = c4[tid];
        float kkv[4] = {kk.x, kk.y, kk.z, kk.w};
        float eev[4] = {ee.x, ee.y, ee.z, ee.w};
        float ppv[4] = {pp.x, pp.y, pp.z, pp.w};
        float bbv[4] = {bb.x, bb.y, bb.z, bb.w};
        float ccv[4] = {cc.x, cc.y, cc.z, cc.w};
        #pragma unroll
        for (int j = 0; j < 4; j++) {
            float ke = kkv[j] * eev[j];
            __half2 e5 = __float2half2_rn(5.0f * eev[j]);
            __half2 kh = __float2half2_rn(kkv[j]);
            __half2 z9 = __float2half2_rn(0.9f * ke);
            __half2 w1 = __float2half2_rn(0.1f * ke);
            uint4 u;
            u.x = *(unsigned*)&e5;
            u.y = *(unsigned*)&kh;
            u.z = *(unsigned*)&z9;
            u.w = *(unsigned*)&w1;
            sA[tid * 4 + j] = u;
            sC[tid * 4 + j] = ccv[j] * ppv[j];
            cb += ccv[j] * bbv[j];
        }
    }
    // block-reduce cb (position-independent term)
    #pragma unroll
    for (int s = 16; s > 0; s >>= 1)
        cb += __shfl_xor_sync(0xFFFFFFFFu, cb, s);
    if ((tid & 31) == 0) sRed[tid >> 5] = cb;
    __syncthreads();
    float bc = (sRed[0] + sRed[1]) + (sRed[2] + sRed[3]) + out_bias[co];

    int cig = tid >> 5;       // ci-group: 0..3 (4 channels each)
    int wo  = tid & 31;       // output col

    const __half2 FIVE2 = __float2half2_rn(5.0f);

    float acc0 = 0.f, acc1 = 0.f, acc2 = 0.f, acc3 = 0.f;

    #pragma unroll 1
    for (int c4i = 0; c4i < 4; c4i++) {
        int ci = cig * 4 + c4i;
        // 5 sliding row-pairs x 3 cols cover all taps of all 4 pixels:
        //  pair A (pixels r0, r0+1):   xh[dy*3+dx]
        //  pair B (pixels r0+2, r0+3): xh[(dy+2)*3+dx]
        __half2 xh[15];
        #pragma unroll
        for (int rr = 0; rr < 5; rr++)
            #pragma unroll
            for (int dx = 0; dx < 3; dx++)
                xh[rr * 3 + dx] = sxp[ci][rr][wo + dx];

        const uint4* pa = &sA[ci * 27];
        const float* pc = &sC[ci * 27];
        #pragma unroll
        for (int q = 0; q < 27; q++) {    // q = nb*9 + dy*3 + dx
            uint4 u  = pa[q];
            float cp = pc[q];
            __half2 e5 = *(__half2*)&u.x;
            __half2 kh = *(__half2*)&u.y;
            __half2 z9 = *(__half2*)&u.z;
            __half2 w1 = *(__half2*)&u.w;
            int ij = q % 9;
            int dy = ij / 3, dxx = ij % 3;
            __half2 xA = xh[dy * 3 + dxx];
            __half2 xB = xh[(dy + 2) * 3 + dxx];
            // pair A
            __half2 gA  = __hfma2(xA, kh, z9);
            __half2 t1A = tanh2_approx(__hfma2(xA, FIVE2, e5));
            __half2 t2A = tanh2_approx(__hfma2(t1A, w1, gA));
            // pair B
            __half2 gB  = __hfma2(xB, kh, z9);
            __half2 t1B = tanh2_approx(__hfma2(xB, FIVE2, e5));
            __half2 t2B = tanh2_approx(__hfma2(t1B, w1, gB));
            acc0 = fmaf(cp, __low2float(t2A),  acc0);
            acc1 = fmaf(cp, __high2float(t2A), acc1);
            acc2 = fmaf(cp, __low2float(t2B),  acc2);
            acc3 = fmaf(cp, __high2float(t2B), acc3);
        }
    }

    if (cig > 0) {
        sP[cig - 1][wo][0] = acc0;
        sP[cig - 1][wo][1] = acc1;
        sP[cig - 1][wo][2] = acc2;
        sP[cig - 1][wo][3] = acc3;
    }
    __syncthreads();
    if (cig == 0) {
        float r[4] = {acc0, acc1, acc2, acc3};
        #pragma unroll
        for (int j = 0; j < 4; j++) {
            float v = ((r[j] + sP[0][wo][j]) + (sP[1][wo][j] + sP[2][wo][j])) + bc;
            out[(((b * NCO + co) * HH + (r0 + j)) * WW) + wo] = v;
        }
    }
}

extern "C" void kernel_launch(void* const* d_in, const int* in_sizes, int n_in,
                              void* d_out, int out_size) {
    const float* x        = (const float*)d_in[0];
    const float* k        = (const float*)d_in[1];
    const float* Ec       = (const float*)d_in[2];
    const float* Ps       = (const float*)d_in[3];
    const float* bias     = (const float*)d_in[4];
    const float* coef     = (const float*)d_in[5];
    const float* out_bias = (const float*)d_in[6];
    float* out = (float*)d_out;

    ferro_main_kernel<<<NBATCH * NCO * 8, 128>>>(x, k, Ec, Ps, bias, coef, out_bias, out);
}

// round 10
// speedup vs baseline: 1.1896x; 1.0885x over previous
#include <cuda_runtime.h>
#include <cuda_bf16.h>
#include <cuda_fp16.h>

#define NCI 16
#define NCO 32
#define NBR 3
#define NTERM (NCI * 9 * NBR)   // 432 per co
#define HH 32
#define WW 32
#define NBATCH 4

__device__ __forceinline__ __half2 tanh2_approx(__half2 x) {
    unsigned xi = *(unsigned*)&x;
    unsigned yi;
    asm("tanh.approx.f16x2 %0, %1;" : "=r"(yi) : "r"(xi));
    return *(__half2*)&yi;
}

// Odd deg-13 polynomial tanh on clamp(y, +-2.6), f16x2, FMA-pipe only.
// Coeffs from Chebyshev expansion of tanh on [-3,3] (pole decomposition).
__device__ __forceinline__ __half2 tanh2_poly(__half2 y) {
    const __half2 M26 = __float2half2_rn(-2.599609375f);
    const __half2 P26 = __float2half2_rn( 2.599609375f);
    const __half2 E13 = __float2half2_rn( 4.4322e-6f);
    const __half2 E11 = __float2half2_rn(-1.56882e-4f);
    const __half2 E9  = __float2half2_rn( 2.3000e-3f);
    const __half2 E7  = __float2half2_rn(-1.83644e-2f);
    const __half2 E5  = __float2half2_rn( 9.01123e-2f);
    const __half2 E3  = __float2half2_rn(-3.062580e-1f);
    const __half2 E1  = __float2half2_rn( 9.938351e-1f);
    __half2 yc = __hmin2(__hmax2(y, M26), P26);
    __half2 z  = __hmul2(yc, yc);
    __half2 p  = __hfma2(z, E13, E11);
    p = __hfma2(p, z, E9);
    p = __hfma2(p, z, E7);
    p = __hfma2(p, z, E5);
    p = __hfma2(p, z, E3);
    p = __hfma2(p, z, E1);
    return __hmul2(yc, p);
}

// Block = (b, co, 4-row tile). 128 threads = 4 ci-groups x 32 cols.
// Each thread: ALL 4 pixels of its tile column (2 vertical half2 pairs),
// 4 of 16 input channels. Inner tanh: poly (FMA pipe) for nb 0,1; MUFU for nb 2.
__global__ __launch_bounds__(128, 7)
void ferro_main_kernel(const float* __restrict__ x,
                       const float* __restrict__ k,
                       const float* __restrict__ Ec,
                       const float* __restrict__ Ps,
                       const float* __restrict__ bias,
                       const float* __restrict__ coef,
                       const float* __restrict__ out_bias,
                       float* __restrict__ out) {
    __shared__ uint4   sA[NTERM];         // {h2(5Ec), h2(k), h2(0.9kEc), h2(0.1kEc)}
    __shared__ float   sC[NTERM];         // coef*Ps (f32)
    __shared__ __half2 sxp[NCI][5][34];   // sliding vertical-pair rows, padded cols
    __shared__ float   sP[3][32][4];      // partials from ci-groups 1..3
    __shared__ float   sRed[4];

    int tid  = threadIdx.x;
    int tile = blockIdx.x & 7;            // 8 tiles of 4 output rows
    int co   = (blockIdx.x >> 3) & 31;
    int b    = blockIdx.x >> 8;
    int r0   = tile * 4;

    // ---- stage x tile as vertical-pair half2: 16 ci x 5 rr x 8 col-groups = 640
    #pragma unroll
    for (int i = 0; i < 5; i++) {
        int idx = tid + i * 128;
        int c4  = idx & 7;
        int rr  = (idx >> 3) % 5;
        int ci  = idx / 40;
        int g0  = r0 - 1 + rr;            // low-half tap row
        int g1  = r0 + rr;                // high-half tap row
        const float* base = x + ((b * NCI + ci) * HH) * WW + c4 * 4;
        float4 v0 = make_float4(0.f, 0.f, 0.f, 0.f);
        float4 v1 = make_float4(0.f, 0.f, 0.f, 0.f);
        if ((unsigned)g0 < 32u) v0 = *(const float4*)(base + g0 * WW);
        if ((unsigned)g1 < 32u) v1 = *(const float4*)(base + g1 * WW);
        int cb0 = c4 * 4 + 1;
        sxp[ci][rr][cb0 + 0] = __floats2half2_rn(v0.x, v1.x);
        sxp[ci][rr][cb0 + 1] = __floats2half2_rn(v0.y, v1.y);
        sxp[ci][rr][cb0 + 2] = __floats2half2_rn(v0.z, v1.z);
        sxp[ci][rr][cb0 + 3] = __floats2half2_rn(v0.w, v1.w);
    }
    if (tid < 80) {                       // zero pad columns: 16 ci x 5 rr
        int ci = tid / 5, rr = tid % 5;
        sxp[ci][rr][0]  = __float2half2_rn(0.f);
        sxp[ci][rr][33] = __float2half2_rn(0.f);
    }

    // ---- pack params for this co (432 terms = 108 float4 groups)
    float cb = 0.0f;
    if (tid < NTERM / 4) {
        const float4* k4 = (const float4*)(k    + co * NTERM);
        const float4* e4 = (const float4*)(Ec   + co * NTERM);
        const float4* p4 = (const float4*)(Ps   + co * NTERM);
        const float4* b4 = (const float4*)(bias + co * NTERM);
        const float4* c4 = (const float4*)(coef + co * NTERM);
        float4 kk = k4[tid], ee = e4[tid], pp = p4[tid], bb = b4[tid], cc = c4[tid];
        float kkv[4] = {kk.x, kk.y, kk.z, kk.w};
        float eev[4] = {ee.x, ee.y, ee.z, ee.w};
        float ppv[4] = {pp.x, pp.y, pp.z, pp.w};
        float bbv[4] = {bb.x, bb.y, bb.z, bb.w};
        float ccv[4] = {cc.x, cc.y, cc.z, cc.w};
        #pragma unroll
        for (int j = 0; j < 4; j++) {
            float ke = kkv[j] * eev[j];
            __half2 e5 = __float2half2_rn(5.0f * eev[j]);
            __half2 kh = __float2half2_rn(kkv[j]);
            __half2 z9 = __float2half2_rn(0.9f * ke);
            __half2 w1 = __float2half2_rn(0.1f * ke);
            uint4 u;
            u.x = *(unsigned*)&e5;
            u.y = *(unsigned*)&kh;
            u.z = *(unsigned*)&z9;
            u.w = *(unsigned*)&w1;
            sA[tid * 4 + j] = u;
            sC[tid * 4 + j] = ccv[j] * ppv[j];
            cb += ccv[j] * bbv[j];
        }
    }
    // block-reduce cb (position-independent term)
    #pragma unroll
    for (int s = 16; s > 0; s >>= 1)
        cb += __shfl_xor_sync(0xFFFFFFFFu, cb, s);
    if ((tid & 31) == 0) sRed[tid >> 5] = cb;
    __syncthreads();
    float bc = (sRed[0] + sRed[1]) + (sRed[2] + sRed[3]) + out_bias[co];

    int cig = tid >> 5;       // ci-group: 0..3 (4 channels each)
    int wo  = tid & 31;       // output col

    const __half2 FIVE2 = __float2half2_rn(5.0f);

    float acc0 = 0.f, acc1 = 0.f, acc2 = 0.f, acc3 = 0.f;

    #pragma unroll 1
    for (int c4i = 0; c4i < 4; c4i++) {
        int ci = cig * 4 + c4i;
        // 5 sliding row-pairs x 3 cols cover all taps of all 4 pixels
        __half2 xh[15];
        #pragma unroll
        for (int rr = 0; rr < 5; rr++)
            #pragma unroll
            for (int dx = 0; dx < 3; dx++)
                xh[rr * 3 + dx] = sxp[ci][rr][wo + dx];

        const uint4* pa = &sA[ci * 27];
        const float* pc = &sC[ci * 27];
        #pragma unroll
        for (int q = 0; q < 27; q++) {    // q = nb*9 + dy*3 + dx
            uint4 u  = pa[q];
            float cp = pc[q];
            __half2 e5 = *(__half2*)&u.x;
            __half2 kh = *(__half2*)&u.y;
            __half2 z9 = *(__half2*)&u.z;
            __half2 w1 = *(__half2*)&u.w;
            int ij = q % 9;
            int dy = ij / 3, dxx = ij % 3;
            __half2 xA = xh[dy * 3 + dxx];
            __half2 xB = xh[(dy + 2) * 3 + dxx];
            __half2 yA = __hfma2(xA, FIVE2, e5);
            __half2 yB = __hfma2(xB, FIVE2, e5);
            __half2 gA = __hfma2(xA, kh, z9);
            __half2 gB = __hfma2(xB, kh, z9);
            __half2 t1A, t1B;
            if (q < 18) {                 // nb 0,1: FMA-pipe polynomial
                t1A = tanh2_poly(yA);
                t1B = tanh2_poly(yB);
            } else {                      // nb 2: MUFU
                t1A = tanh2_approx(yA);
                t1B = tanh2_approx(yB);
            }
            __half2 t2A = tanh2_approx(__hfma2(t1A, w1, gA));
            __half2 t2B = tanh2_approx(__hfma2(t1B, w1, gB));
            acc0 = fmaf(cp, __low2float(t2A),  acc0);
            acc1 = fmaf(cp, __high2float(t2A), acc1);
            acc2 = fmaf(cp, __low2float(t2B),  acc2);
            acc3 = fmaf(cp, __high2float(t2B), acc3);
        }
    }

    if (cig > 0) {
        sP[cig - 1][wo][0] = acc0;
        sP[cig - 1][wo][1] = acc1;
        sP[cig - 1][wo][2] = acc2;
        sP[cig - 1][wo][3] = acc3;
    }
    __syncthreads();
    if (cig == 0) {
        float r[4] = {acc0, acc1, acc2, acc3};
        #pragma unroll
        for (int j = 0; j < 4; j++) {
            float v = ((r[j] + sP[0][wo][j]) + (sP[1][wo][j] + sP[2][wo][j])) + bc;
            out[(((b * NCO + co) * HH + (r0 + j)) * WW) + wo] = v;
        }
    }
}

extern "C" void kernel_launch(void* const* d_in, const int* in_sizes, int n_in,
                              void* d_out, int out_size) {
    const float* x        = (const float*)d_in[0];
    const float* k        = (const float*)d_in[1];
    const float* Ec       = (const float*)d_in[2];
    const float* Ps       = (const float*)d_in[3];
    const float* bias     = (const float*)d_in[4];
    const float* coef     = (const float*)d_in[5];
    const float* out_bias = (const float*)d_in[6];
    float* out = (float*)d_out;

    ferro_main_kernel<<<NBATCH * NCO * 8, 128>>>(x, k, Ec, Ps, bias, coef, out_bias, out);
}